// round 1
// baseline (speedup 1.0000x reference)
#include <cuda_runtime.h>
#include <cuda_bf16.h>
#include <math.h>

#define BB     2
#define CC     256
#define NQ     4096
#define HEADS  4
#define DH     64
#define KK     64
#define GROUPS 32
#define CPG    8        // channels per group
#define EPS    1e-6f

// Scratch (device globals; no allocation allowed)
__device__ float g_h [BB*CC*NQ];   // groupnormed, layout [b][c][n]
__device__ float g_qt[BB*NQ*CC];   // Q, layout [b][n][c]   c = head*64 + d
__device__ float g_kt[BB*NQ*CC];   // K, layout [b][n][c]
__device__ float g_vt[BB*NQ*CC];   // V, layout [b][n][c]
__device__ float g_at[BB*NQ*CC];   // attn out, layout [b][n][c]  c = d*HEADS + h (interleaved!)

// ---------------------------------------------------------------------------
// GroupNorm: grid (GROUPS, B), block 256
// ---------------------------------------------------------------------------
__global__ void gn_kernel(const float* __restrict__ x,
                          const float* __restrict__ scale,
                          const float* __restrict__ bias)
{
    const int g = blockIdx.x, b = blockIdx.y;
    const float* xp = x   + ((size_t)b*CC + g*CPG) * NQ;
    float*       hp = g_h + ((size_t)b*CC + g*CPG) * NQ;
    const int tid = threadIdx.x;
    const int NE  = CPG * NQ;

    float s = 0.f, s2 = 0.f;
    for (int i = tid; i < NE; i += 256) {
        float v = xp[i];
        s += v; s2 += v * v;
    }
    // warp reduce
    #pragma unroll
    for (int o = 16; o; o >>= 1) {
        s  += __shfl_xor_sync(~0u, s,  o);
        s2 += __shfl_xor_sync(~0u, s2, o);
    }
    __shared__ float shs[8], shs2[8];
    __shared__ float mean_s, rstd_s;
    int w = tid >> 5, l = tid & 31;
    if (l == 0) { shs[w] = s; shs2[w] = s2; }
    __syncthreads();
    if (tid == 0) {
        float a = 0.f, c = 0.f;
        #pragma unroll
        for (int i = 0; i < 8; i++) { a += shs[i]; c += shs2[i]; }
        float m   = a / NE;
        float var = c / NE - m * m;
        mean_s = m;
        rstd_s = rsqrtf(var + EPS);
    }
    __syncthreads();
    const float m = mean_s, r = rstd_s;
    for (int i = tid; i < NE; i += 256) {
        int ch = g * CPG + (i >> 12);           // i / NQ
        hp[i] = (xp[i] - m) * r * scale[ch] + bias[ch];
    }
}

// ---------------------------------------------------------------------------
// QKV projection GEMM: outT[b][n][o] = sum_c W[o][c] * g_h[b][c][n] + bias[o]
// Tile 64(n) x 64(o), K-step 16. grid (NQ/64, CC/64, B), block 256.
// which: 0 -> g_qt, 1 -> g_kt, 2 -> g_vt
// ---------------------------------------------------------------------------
__global__ void gemm_qkv(const float* __restrict__ W,
                         const float* __restrict__ bias,
                         int which)
{
    const int nb = blockIdx.x * 64, ob = blockIdx.y * 64, b = blockIdx.z;
    const float* X = g_h + (size_t)b * CC * NQ;                   // [c][n]
    float* O = (which == 0 ? g_qt : which == 1 ? g_kt : g_vt)
               + (size_t)b * NQ * CC;                             // [n][o]

    __shared__ float As[16][68];   // [c][n]
    __shared__ float Bs[16][68];   // [c][o]
    const int tid = threadIdx.x;
    float acc[4][4] = {};

    for (int c0 = 0; c0 < CC; c0 += 16) {
        #pragma unroll
        for (int i = tid; i < 1024; i += 256) {
            int c = i >> 6, n = i & 63;
            As[c][n] = X[(size_t)(c0 + c) * NQ + nb + n];
        }
        #pragma unroll
        for (int i = tid; i < 1024; i += 256) {
            int o = i >> 4, c = i & 15;
            Bs[c][o] = W[(size_t)(ob + o) * CC + c0 + c];
        }
        __syncthreads();
        const int tx = tid & 15, ty = tid >> 4;   // tx -> o, ty -> n
        #pragma unroll
        for (int c = 0; c < 16; c++) {
            float a0[4], b0[4];
            #pragma unroll
            for (int i = 0; i < 4; i++) a0[i] = As[c][ty*4 + i];
            #pragma unroll
            for (int j = 0; j < 4; j++) b0[j] = Bs[c][tx*4 + j];
            #pragma unroll
            for (int i = 0; i < 4; i++)
                #pragma unroll
                for (int j = 0; j < 4; j++)
                    acc[i][j] += a0[i] * b0[j];
        }
        __syncthreads();
    }
    const int tx = tid & 15, ty = tid >> 4;
    #pragma unroll
    for (int i = 0; i < 4; i++) {
        int n = nb + ty*4 + i;
        float4 v;
        v.x = acc[i][0] + bias[ob + tx*4 + 0];
        v.y = acc[i][1] + bias[ob + tx*4 + 1];
        v.z = acc[i][2] + bias[ob + tx*4 + 2];
        v.w = acc[i][3] + bias[ob + tx*4 + 3];
        *(float4*)&O[(size_t)n * CC + ob + tx*4] = v;
    }
}

// ---------------------------------------------------------------------------
// Sparse attention: one warp per (b, n, h). Coalesced 128B gathered rows.
// Masked keys (mask==0) are skipped entirely (warp-uniform branch).
// Output channel order is the reference's interleave: c = d*HEADS + h.
// ---------------------------------------------------------------------------
__global__ void attn_kernel(const int* __restrict__ mask,
                            const int* __restrict__ aidx)
{
    const int gw   = (blockIdx.x * blockDim.x + threadIdx.x) >> 5;
    const int lane = threadIdx.x & 31;
    const int h = gw & (HEADS - 1);
    const int n = (gw >> 2) & (NQ - 1);
    const int b = gw >> 14;

    const float* qt  = g_qt + ((size_t)b * NQ + n) * CC + h * DH;
    const float* ktb = g_kt + (size_t)b * NQ * CC + h * DH;
    const float* vtb = g_vt + (size_t)b * NQ * CC + h * DH;

    const float q0 = qt[lane], q1 = qt[lane + 32];

    // each lane caches index/mask for kk = lane and kk = lane+32
    const int idx0 = aidx[n * KK + lane];
    const int idx1 = aidx[n * KK + lane + 32];
    const int m0   = mask[n * KK + lane];
    const int m1   = mask[n * KK + lane + 32];

    float l0 = -INFINITY, l1 = -INFINITY;

    #pragma unroll 4
    for (int kk = 0; kk < KK; kk++) {
        int mk  = __shfl_sync(~0u, (kk < 32) ? m0   : m1,   kk & 31);
        if (!mk) continue;                       // warp-uniform skip
        int idx = __shfl_sync(~0u, (kk < 32) ? idx0 : idx1, kk & 31);
        const float* kr = ktb + (size_t)idx * CC;
        float p = q0 * kr[lane] + q1 * kr[lane + 32];
        #pragma unroll
        for (int o = 16; o; o >>= 1) p += __shfl_xor_sync(~0u, p, o);
        if ((kk & 31) == lane) { if (kk < 32) l0 = p; else l1 = p; }
    }
    if (!m0) l0 = -INFINITY;
    if (!m1) l1 = -INFINITY;

    float mx = fmaxf(l0, l1);
    #pragma unroll
    for (int o = 16; o; o >>= 1) mx = fmaxf(mx, __shfl_xor_sync(~0u, mx, o));
    float e0 = __expf(l0 - mx), e1 = __expf(l1 - mx);
    float s = e0 + e1;
    #pragma unroll
    for (int o = 16; o; o >>= 1) s += __shfl_xor_sync(~0u, s, o);
    const float inv = 1.f / s;
    const float w0 = e0 * inv, w1 = e1 * inv;

    float a0 = 0.f, a1 = 0.f;
    #pragma unroll 4
    for (int kk = 0; kk < KK; kk++) {
        float wv = __shfl_sync(~0u, (kk < 32) ? w0 : w1, kk & 31);
        if (wv == 0.f) continue;                 // warp-uniform skip (masked)
        int idx  = __shfl_sync(~0u, (kk < 32) ? idx0 : idx1, kk & 31);
        const float* vr = vtb + (size_t)idx * CC;
        a0 += wv * vr[lane];
        a1 += wv * vr[lane + 32];
    }
    // interleaved channel order: c = d*HEADS + h
    float* at = g_at + ((size_t)b * NQ + n) * CC;
    at[(lane)      * HEADS + h] = a0;
    at[(lane + 32) * HEADS + h] = a1;
}

// ---------------------------------------------------------------------------
// Output projection + residual:
// out[b][o][n] = x[b][o][n] + sum_c Wo[o][c] * g_at[b][n][c] + bo[o]
// Tile 64(o) x 64(n), K-step 16. grid (NQ/64, CC/64, B), block 256.
// ---------------------------------------------------------------------------
__global__ void gemm_out(const float* __restrict__ Wo,
                         const float* __restrict__ bo,
                         const float* __restrict__ x,
                         float* __restrict__ out)
{
    const int nb = blockIdx.x * 64, ob = blockIdx.y * 64, b = blockIdx.z;
    const float* A = g_at + (size_t)b * NQ * CC;   // [n][c]

    __shared__ float Ws [16][68];   // [c][o]
    __shared__ float Ats[16][68];   // [c][n]
    const int tid = threadIdx.x;
    float acc[4][4] = {};

    for (int c0 = 0; c0 < CC; c0 += 16) {
        #pragma unroll
        for (int i = tid; i < 1024; i += 256) {
            int o = i >> 4, c = i & 15;
            Ws[c][o] = Wo[(size_t)(ob + o) * CC + c0 + c];
        }
        #pragma unroll
        for (int i = tid; i < 1024; i += 256) {
            int n = i >> 4, c = i & 15;
            Ats[c][n] = A[(size_t)(nb + n) * CC + c0 + c];
        }
        __syncthreads();
        const int tx = tid & 15, ty = tid >> 4;   // tx -> n, ty -> o
        #pragma unroll
        for (int c = 0; c < 16; c++) {
            float a0[4], b0[4];
            #pragma unroll
            for (int i = 0; i < 4; i++) a0[i] = Ws[c][ty*4 + i];
            #pragma unroll
            for (int j = 0; j < 4; j++) b0[j] = Ats[c][tx*4 + j];
            #pragma unroll
            for (int i = 0; i < 4; i++)
                #pragma unroll
                for (int j = 0; j < 4; j++)
                    acc[i][j] += a0[i] * b0[j];
        }
        __syncthreads();
    }
    const int tx = tid & 15, ty = tid >> 4;
    const float* xp = x   + (size_t)b * CC * NQ;
    float*       op = out + (size_t)b * CC * NQ;
    #pragma unroll
    for (int i = 0; i < 4; i++) {
        int o = ob + ty*4 + i;
        size_t base = (size_t)o * NQ + nb + tx*4;
        float4 xv = *(const float4*)&xp[base];
        float bb = bo[o];
        float4 v;
        v.x = acc[i][0] + bb + xv.x;
        v.y = acc[i][1] + bb + xv.y;
        v.z = acc[i][2] + bb + xv.z;
        v.w = acc[i][3] + bb + xv.w;
        *(float4*)&op[base] = v;
    }
}

// ---------------------------------------------------------------------------
extern "C" void kernel_launch(void* const* d_in, const int* in_sizes, int n_in,
                              void* d_out, int out_size)
{
    const float* x    = (const float*)d_in[0];
    const int*   mask = (const int*)  d_in[1];
    const int*   aidx = (const int*)  d_in[2];
    const float* gsc  = (const float*)d_in[3];
    const float* gbi  = (const float*)d_in[4];
    const float* wq   = (const float*)d_in[5];
    const float* bq   = (const float*)d_in[6];
    const float* wk   = (const float*)d_in[7];
    const float* bk   = (const float*)d_in[8];
    const float* wv   = (const float*)d_in[9];
    const float* bv   = (const float*)d_in[10];
    const float* wo   = (const float*)d_in[11];
    const float* bo   = (const float*)d_in[12];
    float* out = (float*)d_out;

    gn_kernel<<<dim3(GROUPS, BB), 256>>>(x, gsc, gbi);

    dim3 ggrid(NQ / 64, CC / 64, BB);
    gemm_qkv<<<ggrid, 256>>>(wq, bq, 0);
    gemm_qkv<<<ggrid, 256>>>(wk, bk, 1);
    gemm_qkv<<<ggrid, 256>>>(wv, bv, 2);

    // one warp per (b, n, h): B*NQ*HEADS warps
    int total_warps = BB * NQ * HEADS;
    attn_kernel<<<total_warps * 32 / 256, 256>>>(mask, aidx);

    gemm_out<<<ggrid, 256>>>(wo, bo, x, out);
}

// round 2
// speedup vs baseline: 1.2411x; 1.2411x over previous
#include <cuda_runtime.h>
#include <cuda_bf16.h>
#include <math.h>

#define BB     2
#define CC     256
#define NQ     4096
#define HEADS  4
#define DH     64
#define KK     64
#define GROUPS 32
#define CPG    8
#define EPS    1e-6f

// Scratch (device globals; no allocation allowed)
__device__ float         g_h [BB*CC*NQ];   // groupnormed, [b][c][n]
__device__ float         g_qt[BB*NQ*CC];   // Q fp32, [b][n][c]  c = head*64 + d
__device__ __nv_bfloat16 g_kb[BB*NQ*CC];   // K bf16, [b][n][c]
__device__ __nv_bfloat16 g_vb[BB*NQ*CC];   // V bf16, [b][n][c]
__device__ float         g_at[BB*NQ*CC];   // attn out, [b][n][c]  c = d*HEADS + h

// ---------------------------------------------------------------------------
// GroupNorm: grid (GROUPS, B), block 256
// ---------------------------------------------------------------------------
__global__ void gn_kernel(const float* __restrict__ x,
                          const float* __restrict__ scale,
                          const float* __restrict__ bias)
{
    const int g = blockIdx.x, b = blockIdx.y;
    const float* xp = x   + ((size_t)b*CC + g*CPG) * NQ;
    float*       hp = g_h + ((size_t)b*CC + g*CPG) * NQ;
    const int tid = threadIdx.x;
    const int NE  = CPG * NQ;

    float s = 0.f, s2 = 0.f;
    for (int i = tid; i < NE; i += 256) {
        float v = xp[i];
        s += v; s2 += v * v;
    }
    #pragma unroll
    for (int o = 16; o; o >>= 1) {
        s  += __shfl_xor_sync(~0u, s,  o);
        s2 += __shfl_xor_sync(~0u, s2, o);
    }
    __shared__ float shs[8], shs2[8];
    __shared__ float mean_s, rstd_s;
    int w = tid >> 5, l = tid & 31;
    if (l == 0) { shs[w] = s; shs2[w] = s2; }
    __syncthreads();
    if (tid == 0) {
        float a = 0.f, c = 0.f;
        #pragma unroll
        for (int i = 0; i < 8; i++) { a += shs[i]; c += shs2[i]; }
        float m   = a / NE;
        float var = c / NE - m * m;
        mean_s = m;
        rstd_s = rsqrtf(var + EPS);
    }
    __syncthreads();
    const float m = mean_s, r = rstd_s;
    for (int i = tid; i < NE; i += 256) {
        int ch = g * CPG + (i >> 12);
        hp[i] = (xp[i] - m) * r * scale[ch] + bias[ch];
    }
}

// ---------------------------------------------------------------------------
// Fused QKV GEMM: O[b][n][o] = sum_c W[o][c] * g_h[b][c][n] + bias[o]
// Tile 128(n) x 64(o), K-step 16, per-thread 8x4. grid (NQ/128, 12, B).
// blockIdx.y: [0..3] -> Q (fp32), [4..7] -> K (bf16), [8..11] -> V (bf16)
// ---------------------------------------------------------------------------
__global__ void __launch_bounds__(256)
gemm_qkv(const float* __restrict__ wq, const float* __restrict__ bq,
         const float* __restrict__ wk, const float* __restrict__ bk,
         const float* __restrict__ wv, const float* __restrict__ bv)
{
    const int nb    = blockIdx.x * 128;
    const int which = blockIdx.y >> 2;
    const int ob    = (blockIdx.y & 3) * 64;
    const int b     = blockIdx.z;

    const float* W    = which == 0 ? wq : which == 1 ? wk : wv;
    const float* bias = which == 0 ? bq : which == 1 ? bk : bv;
    const float* X = g_h + (size_t)b * CC * NQ;   // [c][n]

    __shared__ float As[16][132];   // [c][n]
    __shared__ float Bs[16][68];    // [c][o]
    const int tid = threadIdx.x;
    float acc[8][4] = {};

    for (int c0 = 0; c0 < CC; c0 += 16) {
        #pragma unroll
        for (int j = 0; j < 8; j++) {
            int i = tid + j * 256;
            int c = i >> 7, n = i & 127;
            As[c][n] = X[(size_t)(c0 + c) * NQ + nb + n];
        }
        #pragma unroll
        for (int j = 0; j < 4; j++) {
            int i = tid + j * 256;
            int o = i >> 4, c = i & 15;
            Bs[c][o] = W[(size_t)(ob + o) * CC + c0 + c];
        }
        __syncthreads();
        const int tx = tid & 15, ty = tid >> 4;   // tx -> o(4), ty -> n(8)
        #pragma unroll
        for (int c = 0; c < 16; c++) {
            float4 a0 = *(const float4*)&As[c][ty * 8];
            float4 a1 = *(const float4*)&As[c][ty * 8 + 4];
            float4 bb = *(const float4*)&Bs[c][tx * 4];
            float av[8] = {a0.x, a0.y, a0.z, a0.w, a1.x, a1.y, a1.z, a1.w};
            float bw[4] = {bb.x, bb.y, bb.z, bb.w};
            #pragma unroll
            for (int i = 0; i < 8; i++)
                #pragma unroll
                for (int j = 0; j < 4; j++)
                    acc[i][j] += av[i] * bw[j];
        }
        __syncthreads();
    }

    const int tx = tid & 15, ty = tid >> 4;
    const float b0 = bias[ob + tx*4 + 0];
    const float b1 = bias[ob + tx*4 + 1];
    const float b2 = bias[ob + tx*4 + 2];
    const float b3 = bias[ob + tx*4 + 3];

    if (which == 0) {
        float* O = g_qt + (size_t)b * NQ * CC;
        #pragma unroll
        for (int i = 0; i < 8; i++) {
            int n = nb + ty * 8 + i;
            float4 v = {acc[i][0] + b0, acc[i][1] + b1,
                        acc[i][2] + b2, acc[i][3] + b3};
            *(float4*)&O[(size_t)n * CC + ob + tx*4] = v;
        }
    } else {
        __nv_bfloat16* O = (which == 1 ? g_kb : g_vb) + (size_t)b * NQ * CC;
        #pragma unroll
        for (int i = 0; i < 8; i++) {
            int n = nb + ty * 8 + i;
            __nv_bfloat162 p0 = {__float2bfloat16_rn(acc[i][0] + b0),
                                 __float2bfloat16_rn(acc[i][1] + b1)};
            __nv_bfloat162 p1 = {__float2bfloat16_rn(acc[i][2] + b2),
                                 __float2bfloat16_rn(acc[i][3] + b3)};
            __nv_bfloat162* dst = (__nv_bfloat162*)&O[(size_t)n * CC + ob + tx*4];
            dst[0] = p0;
            dst[1] = p1;
        }
    }
}

// ---------------------------------------------------------------------------
// Sparse attention: one warp per (b, n, h). bf16 K/V gathered rows (128B).
// Each lane covers d = 2*lane, 2*lane+1. Masked keys skipped warp-uniformly.
// ---------------------------------------------------------------------------
__global__ void __launch_bounds__(256)
attn_kernel(const int* __restrict__ mask, const int* __restrict__ aidx)
{
    const int gw   = (blockIdx.x * blockDim.x + threadIdx.x) >> 5;
    const int lane = threadIdx.x & 31;
    const int h = gw & (HEADS - 1);
    const int n = (gw >> 2) & (NQ - 1);
    const int b = gw >> 14;

    const float*         qt  = g_qt + ((size_t)b * NQ + n) * CC + h * DH;
    const __nv_bfloat16* ktb = g_kb + (size_t)b * NQ * CC + h * DH;
    const __nv_bfloat16* vtb = g_vb + (size_t)b * NQ * CC + h * DH;

    const float q0 = qt[2*lane], q1 = qt[2*lane + 1];

    const int idx0 = aidx[n * KK + lane];
    const int idx1 = aidx[n * KK + lane + 32];
    const int m0   = mask[n * KK + lane];
    const int m1   = mask[n * KK + lane + 32];

    float l0 = -INFINITY, l1 = -INFINITY;

    #pragma unroll 4
    for (int kk = 0; kk < KK; kk++) {
        int mk  = __shfl_sync(~0u, (kk < 32) ? m0   : m1,   kk & 31);
        if (!mk) continue;
        int idx = __shfl_sync(~0u, (kk < 32) ? idx0 : idx1, kk & 31);
        const __nv_bfloat162* kr = (const __nv_bfloat162*)(ktb + (size_t)idx * CC);
        float2 kf = __bfloat1622float2(kr[lane]);
        float p = q0 * kf.x + q1 * kf.y;
        #pragma unroll
        for (int o = 16; o; o >>= 1) p += __shfl_xor_sync(~0u, p, o);
        if ((kk & 31) == lane) { if (kk < 32) l0 = p; else l1 = p; }
    }
    if (!m0) l0 = -INFINITY;
    if (!m1) l1 = -INFINITY;

    float mx = fmaxf(l0, l1);
    #pragma unroll
    for (int o = 16; o; o >>= 1) mx = fmaxf(mx, __shfl_xor_sync(~0u, mx, o));
    float e0 = __expf(l0 - mx), e1 = __expf(l1 - mx);
    float s = e0 + e1;
    #pragma unroll
    for (int o = 16; o; o >>= 1) s += __shfl_xor_sync(~0u, s, o);
    const float inv = 1.f / s;
    const float w0 = e0 * inv, w1 = e1 * inv;

    float a0 = 0.f, a1 = 0.f;
    #pragma unroll 4
    for (int kk = 0; kk < KK; kk++) {
        float wv = __shfl_sync(~0u, (kk < 32) ? w0 : w1, kk & 31);
        if (wv == 0.f) continue;
        int idx  = __shfl_sync(~0u, (kk < 32) ? idx0 : idx1, kk & 31);
        const __nv_bfloat162* vr = (const __nv_bfloat162*)(vtb + (size_t)idx * CC);
        float2 vf = __bfloat1622float2(vr[lane]);
        a0 += wv * vf.x;
        a1 += wv * vf.y;
    }
    // interleaved channel order: c = d*HEADS + h
    float* at = g_at + ((size_t)b * NQ + n) * CC;
    at[(2*lane)     * HEADS + h] = a0;
    at[(2*lane + 1) * HEADS + h] = a1;
}

// ---------------------------------------------------------------------------
// Output projection + residual:
// out[b][o][n] = x[b][o][n] + sum_c Wo[o][c] * g_at[b][n][c] + bo[o]
// Tile 64(o) x 128(n), K-step 16, per-thread 4x8. grid (NQ/128, CC/64, B).
// ---------------------------------------------------------------------------
__global__ void __launch_bounds__(256)
gemm_out(const float* __restrict__ Wo, const float* __restrict__ bo,
         const float* __restrict__ x,  float* __restrict__ out)
{
    const int nb = blockIdx.x * 128, ob = blockIdx.y * 64, b = blockIdx.z;
    const float* A = g_at + (size_t)b * NQ * CC;   // [n][c]

    __shared__ float Ws [16][68];    // [c][o]
    __shared__ float Ats[16][132];   // [c][n]
    const int tid = threadIdx.x;
    float acc[4][8] = {};

    for (int c0 = 0; c0 < CC; c0 += 16) {
        #pragma unroll
        for (int j = 0; j < 4; j++) {
            int i = tid + j * 256;
            int o = i >> 4, c = i & 15;
            Ws[c][o] = Wo[(size_t)(ob + o) * CC + c0 + c];
        }
        #pragma unroll
        for (int j = 0; j < 8; j++) {
            int i = tid + j * 256;
            int n = i >> 4, c = i & 15;
            Ats[c][n] = A[(size_t)(nb + n) * CC + c0 + c];
        }
        __syncthreads();
        const int tx = tid & 15, ty = tid >> 4;   // tx -> n(8), ty -> o(4)
        #pragma unroll
        for (int c = 0; c < 16; c++) {
            float4 w4 = *(const float4*)&Ws[c][ty * 4];
            float4 n0 = *(const float4*)&Ats[c][tx * 8];
            float4 n1 = *(const float4*)&Ats[c][tx * 8 + 4];
            float wv[4] = {w4.x, w4.y, w4.z, w4.w};
            float nv[8] = {n0.x, n0.y, n0.z, n0.w, n1.x, n1.y, n1.z, n1.w};
            #pragma unroll
            for (int i = 0; i < 4; i++)
                #pragma unroll
                for (int j = 0; j < 8; j++)
                    acc[i][j] += wv[i] * nv[j];
        }
        __syncthreads();
    }

    const int tx = tid & 15, ty = tid >> 4;
    const float* xp = x   + (size_t)b * CC * NQ;
    float*       op = out + (size_t)b * CC * NQ;
    #pragma unroll
    for (int i = 0; i < 4; i++) {
        int o = ob + ty * 4 + i;
        size_t base = (size_t)o * NQ + nb + tx * 8;
        float bb = bo[o];
        float4 x0 = *(const float4*)&xp[base];
        float4 x1 = *(const float4*)&xp[base + 4];
        float4 v0 = {acc[i][0] + bb + x0.x, acc[i][1] + bb + x0.y,
                     acc[i][2] + bb + x0.z, acc[i][3] + bb + x0.w};
        float4 v1 = {acc[i][4] + bb + x1.x, acc[i][5] + bb + x1.y,
                     acc[i][6] + bb + x1.z, acc[i][7] + bb + x1.w};
        *(float4*)&op[base]     = v0;
        *(float4*)&op[base + 4] = v1;
    }
}

// ---------------------------------------------------------------------------
extern "C" void kernel_launch(void* const* d_in, const int* in_sizes, int n_in,
                              void* d_out, int out_size)
{
    const float* x    = (const float*)d_in[0];
    const int*   mask = (const int*)  d_in[1];
    const int*   aidx = (const int*)  d_in[2];
    const float* gsc  = (const float*)d_in[3];
    const float* gbi  = (const float*)d_in[4];
    const float* wq   = (const float*)d_in[5];
    const float* bq   = (const float*)d_in[6];
    const float* wk   = (const float*)d_in[7];
    const float* bk   = (const float*)d_in[8];
    const float* wv   = (const float*)d_in[9];
    const float* bv   = (const float*)d_in[10];
    const float* wo   = (const float*)d_in[11];
    const float* bo   = (const float*)d_in[12];
    float* out = (float*)d_out;

    gn_kernel<<<dim3(GROUPS, BB), 256>>>(x, gsc, gbi);

    gemm_qkv<<<dim3(NQ / 128, 12, BB), 256>>>(wq, bq, wk, bk, wv, bv);

    int total_warps = BB * NQ * HEADS;
    attn_kernel<<<total_warps * 32 / 256, 256>>>(mask, aidx);

    gemm_out<<<dim3(NQ / 128, CC / 64, BB), 256>>>(wo, bo, x, out);
}

// round 3
// speedup vs baseline: 1.9695x; 1.5869x over previous
#include <cuda_runtime.h>
#include <cuda_bf16.h>
#include <math.h>

#define BB     2
#define CC     256
#define NQ     4096
#define HEADS  4
#define DH     64
#define KK     64
#define GROUPS 32
#define CPG    8
#define EPS    1e-6f
#define LDC    36        // smem row pitch (floats) -> conflict-free mma frag loads

// Scratch (device globals; no allocation allowed)
__device__ float         g_h [BB*CC*NQ];   // groupnormed, [b][c][n]
__device__ float         g_qt[BB*NQ*CC];   // Q fp32, [b][n][c]  c = head*64 + d
__device__ __nv_bfloat16 g_kb[BB*NQ*CC];   // K bf16, [b][n][c]
__device__ __nv_bfloat16 g_vb[BB*NQ*CC];   // V bf16, [b][n][c]
__device__ float         g_at[BB*NQ*CC];   // attn out, [b][n][c]  c = d*HEADS + h

// ---------------------------------------------------------------------------
// tf32 helpers
// ---------------------------------------------------------------------------
__device__ __forceinline__ unsigned f2tf32(float f) {
    unsigned r;
    asm("cvt.rna.tf32.f32 %0, %1;" : "=r"(r) : "f"(f));
    return r;
}

__device__ __forceinline__ void mma1688(float d[4], const unsigned a[4],
                                        const unsigned b[2]) {
    asm("mma.sync.aligned.m16n8k8.row.col.f32.tf32.tf32.f32 "
        "{%0,%1,%2,%3}, {%4,%5,%6,%7}, {%8,%9}, {%0,%1,%2,%3};"
        : "+f"(d[0]), "+f"(d[1]), "+f"(d[2]), "+f"(d[3])
        : "r"(a[0]), "r"(a[1]), "r"(a[2]), "r"(a[3]),
          "r"(b[0]), "r"(b[1]));
}

// ---------------------------------------------------------------------------
// GroupNorm: grid (GROUPS, B), block 256
// ---------------------------------------------------------------------------
__global__ void gn_kernel(const float* __restrict__ x,
                          const float* __restrict__ scale,
                          const float* __restrict__ bias)
{
    const int g = blockIdx.x, b = blockIdx.y;
    const float* xp = x   + ((size_t)b*CC + g*CPG) * NQ;
    float*       hp = g_h + ((size_t)b*CC + g*CPG) * NQ;
    const int tid = threadIdx.x;
    const int NE  = CPG * NQ;

    float s = 0.f, s2 = 0.f;
    for (int i = tid; i < NE; i += 256) {
        float v = xp[i];
        s += v; s2 += v * v;
    }
    #pragma unroll
    for (int o = 16; o; o >>= 1) {
        s  += __shfl_xor_sync(~0u, s,  o);
        s2 += __shfl_xor_sync(~0u, s2, o);
    }
    __shared__ float shs[8], shs2[8];
    __shared__ float mean_s, rstd_s;
    int w = tid >> 5, l = tid & 31;
    if (l == 0) { shs[w] = s; shs2[w] = s2; }
    __syncthreads();
    if (tid == 0) {
        float a = 0.f, c = 0.f;
        #pragma unroll
        for (int i = 0; i < 8; i++) { a += shs[i]; c += shs2[i]; }
        float m   = a / NE;
        float var = c / NE - m * m;
        mean_s = m;
        rstd_s = rsqrtf(var + EPS);
    }
    __syncthreads();
    const float m = mean_s, r = rstd_s;
    for (int i = tid; i < NE; i += 256) {
        int ch = g * CPG + (i >> 12);
        hp[i] = (xp[i] - m) * r * scale[ch] + bias[ch];
    }
}

// ---------------------------------------------------------------------------
// Fused QKV GEMM (tf32 tensor core):
// O[b][n][o] = sum_c W[o][c] * g_h[b][c][n] + bias[o]
// Block tile 128(n=M) x 128(o=N), K-step 32. 8 warps (2x4), warp 64x32.
// A[n][c] = transpose of g_h tile (staged); B[o][c] = W tile (direct, col-maj frag).
// grid (NQ/128, 6, B): blockIdx.y>>1 = which (Q/K/V), (y&1)*128 = o-block.
// ---------------------------------------------------------------------------
__global__ void __launch_bounds__(256)
gemm_qkv(const float* __restrict__ wq, const float* __restrict__ bq,
         const float* __restrict__ wk, const float* __restrict__ bk,
         const float* __restrict__ wv, const float* __restrict__ bv)
{
    const int nb    = blockIdx.x * 128;
    const int which = blockIdx.y >> 1;
    const int ob    = (blockIdx.y & 1) * 128;
    const int b     = blockIdx.z;

    const float* W    = which == 0 ? wq : which == 1 ? wk : wv;
    const float* bias = which == 0 ? bq : which == 1 ? bk : bv;
    const float* X = g_h + (size_t)b * CC * NQ;   // [c][n]

    __shared__ unsigned As[128][LDC];   // [n][c] tf32
    __shared__ unsigned Bs[128][LDC];   // [o][c] tf32

    const int tid  = threadIdx.x;
    const int wid  = tid >> 5, lane = tid & 31;
    const int wm   = wid & 1,  wn   = wid >> 1;
    const int g    = lane >> 2, t   = lane & 3;

    float acc[4][4][4];
    #pragma unroll
    for (int i = 0; i < 4; i++)
        #pragma unroll
        for (int j = 0; j < 4; j++)
            #pragma unroll
            for (int r = 0; r < 4; r++) acc[i][j][r] = 0.f;

    for (int c0 = 0; c0 < CC; c0 += 32) {
        // As: transpose-stage X[c][n] -> As[n][c]
        #pragma unroll
        for (int cc = 0; cc < 32; cc += 8) {
            #pragma unroll
            for (int nn = 0; nn < 128; nn += 32) {
                float v = X[(size_t)(c0 + cc + wid) * NQ + nb + nn + lane];
                As[nn + lane][cc + wid] = f2tf32(v);
            }
        }
        // Bs: W[o][c] direct (c contiguous), float4 loads
        {
            int c4 = (tid & 7) * 4;
            int o  = tid >> 3;
            #pragma unroll
            for (int oo = 0; oo < 128; oo += 32) {
                float4 v = *(const float4*)&W[(size_t)(ob + oo + o) * CC + c0 + c4];
                unsigned* dst = &Bs[oo + o][c4];
                dst[0] = f2tf32(v.x); dst[1] = f2tf32(v.y);
                dst[2] = f2tf32(v.z); dst[3] = f2tf32(v.w);
            }
        }
        __syncthreads();

        #pragma unroll
        for (int k8 = 0; k8 < 32; k8 += 8) {
            unsigned afr[4][4], bfr[4][2];
            #pragma unroll
            for (int mt = 0; mt < 4; mt++) {
                int row = wm * 64 + mt * 16;
                afr[mt][0] = As[row + g    ][k8 + t];
                afr[mt][1] = As[row + 8 + g][k8 + t];
                afr[mt][2] = As[row + g    ][k8 + 4 + t];
                afr[mt][3] = As[row + 8 + g][k8 + 4 + t];
            }
            #pragma unroll
            for (int nt = 0; nt < 4; nt++) {
                int col = wn * 32 + nt * 8;
                bfr[nt][0] = Bs[col + g][k8 + t];
                bfr[nt][1] = Bs[col + g][k8 + 4 + t];
            }
            #pragma unroll
            for (int mt = 0; mt < 4; mt++)
                #pragma unroll
                for (int nt = 0; nt < 4; nt++)
                    mma1688(acc[mt][nt], afr[mt], bfr[nt]);
        }
        __syncthreads();
    }

    // Epilogue
    if (which == 0) {
        float* O = g_qt + (size_t)b * NQ * CC;
        #pragma unroll
        for (int nt = 0; nt < 4; nt++) {
            int o = ob + wn * 32 + nt * 8 + 2 * t;
            float bb0 = bias[o], bb1 = bias[o + 1];
            #pragma unroll
            for (int mt = 0; mt < 4; mt++) {
                int n0 = nb + wm * 64 + mt * 16 + g;
                float2 v0 = {acc[mt][nt][0] + bb0, acc[mt][nt][1] + bb1};
                float2 v1 = {acc[mt][nt][2] + bb0, acc[mt][nt][3] + bb1};
                *(float2*)&O[(size_t)n0 * CC + o]       = v0;
                *(float2*)&O[(size_t)(n0 + 8) * CC + o] = v1;
            }
        }
    } else {
        __nv_bfloat16* O = (which == 1 ? g_kb : g_vb) + (size_t)b * NQ * CC;
        #pragma unroll
        for (int nt = 0; nt < 4; nt++) {
            int o = ob + wn * 32 + nt * 8 + 2 * t;
            float bb0 = bias[o], bb1 = bias[o + 1];
            #pragma unroll
            for (int mt = 0; mt < 4; mt++) {
                int n0 = nb + wm * 64 + mt * 16 + g;
                __nv_bfloat162 v0 = {__float2bfloat16_rn(acc[mt][nt][0] + bb0),
                                     __float2bfloat16_rn(acc[mt][nt][1] + bb1)};
                __nv_bfloat162 v1 = {__float2bfloat16_rn(acc[mt][nt][2] + bb0),
                                     __float2bfloat16_rn(acc[mt][nt][3] + bb1)};
                *(__nv_bfloat162*)&O[(size_t)n0 * CC + o]       = v0;
                *(__nv_bfloat162*)&O[(size_t)(n0 + 8) * CC + o] = v1;
            }
        }
    }
}

// ---------------------------------------------------------------------------
// Sparse attention: one warp per (b, n, h). bf16 K/V gathered rows (128B).
// ---------------------------------------------------------------------------
__global__ void __launch_bounds__(256)
attn_kernel(const int* __restrict__ mask, const int* __restrict__ aidx)
{
    const int gw   = (blockIdx.x * blockDim.x + threadIdx.x) >> 5;
    const int lane = threadIdx.x & 31;
    const int h = gw & (HEADS - 1);
    const int n = (gw >> 2) & (NQ - 1);
    const int b = gw >> 14;

    const float*         qt  = g_qt + ((size_t)b * NQ + n) * CC + h * DH;
    const __nv_bfloat16* ktb = g_kb + (size_t)b * NQ * CC + h * DH;
    const __nv_bfloat16* vtb = g_vb + (size_t)b * NQ * CC + h * DH;

    const float q0 = qt[2*lane], q1 = qt[2*lane + 1];

    const int idx0 = aidx[n * KK + lane];
    const int idx1 = aidx[n * KK + lane + 32];
    const int m0   = mask[n * KK + lane];
    const int m1   = mask[n * KK + lane + 32];

    float l0 = -INFINITY, l1 = -INFINITY;

    #pragma unroll 4
    for (int kk = 0; kk < KK; kk++) {
        int mk  = __shfl_sync(~0u, (kk < 32) ? m0   : m1,   kk & 31);
        if (!mk) continue;
        int idx = __shfl_sync(~0u, (kk < 32) ? idx0 : idx1, kk & 31);
        const __nv_bfloat162* kr = (const __nv_bfloat162*)(ktb + (size_t)idx * CC);
        float2 kf = __bfloat1622float2(kr[lane]);
        float p = q0 * kf.x + q1 * kf.y;
        #pragma unroll
        for (int o = 16; o; o >>= 1) p += __shfl_xor_sync(~0u, p, o);
        if ((kk & 31) == lane) { if (kk < 32) l0 = p; else l1 = p; }
    }
    if (!m0) l0 = -INFINITY;
    if (!m1) l1 = -INFINITY;

    float mx = fmaxf(l0, l1);
    #pragma unroll
    for (int o = 16; o; o >>= 1) mx = fmaxf(mx, __shfl_xor_sync(~0u, mx, o));
    float e0 = __expf(l0 - mx), e1 = __expf(l1 - mx);
    float s = e0 + e1;
    #pragma unroll
    for (int o = 16; o; o >>= 1) s += __shfl_xor_sync(~0u, s, o);
    const float inv = 1.f / s;
    const float w0 = e0 * inv, w1 = e1 * inv;

    float a0 = 0.f, a1 = 0.f;
    #pragma unroll 4
    for (int kk = 0; kk < KK; kk++) {
        float wv = __shfl_sync(~0u, (kk < 32) ? w0 : w1, kk & 31);
        if (wv == 0.f) continue;
        int idx  = __shfl_sync(~0u, (kk < 32) ? idx0 : idx1, kk & 31);
        const __nv_bfloat162* vr = (const __nv_bfloat162*)(vtb + (size_t)idx * CC);
        float2 vf = __bfloat1622float2(vr[lane]);
        a0 += wv * vf.x;
        a1 += wv * vf.y;
    }
    float* at = g_at + ((size_t)b * NQ + n) * CC;
    at[(2*lane)     * HEADS + h] = a0;
    at[(2*lane + 1) * HEADS + h] = a1;
}

// ---------------------------------------------------------------------------
// Output projection + residual (tf32 tensor core):
// out[b][o][n] = x[b][o][n] + sum_c Wo[o][c] * g_at[b][n][c] + bo[o]
// Block tile 128(o=M) x 128(n=N), K-step 32. A = Wo (direct), B = g_at (direct).
// grid (NQ/128, CC/128, B).
// ---------------------------------------------------------------------------
__global__ void __launch_bounds__(256)
gemm_out(const float* __restrict__ Wo, const float* __restrict__ bo,
         const float* __restrict__ x,  float* __restrict__ out)
{
    const int nb = blockIdx.x * 128, ob = blockIdx.y * 128, b = blockIdx.z;
    const float* A = g_at + (size_t)b * NQ * CC;   // [n][c]

    __shared__ unsigned As[128][LDC];   // [o][c] tf32
    __shared__ unsigned Bs[128][LDC];   // [n][c] tf32

    const int tid  = threadIdx.x;
    const int wid  = tid >> 5, lane = tid & 31;
    const int wm   = wid & 1,  wn   = wid >> 1;
    const int g    = lane >> 2, t   = lane & 3;

    float acc[4][4][4];
    #pragma unroll
    for (int i = 0; i < 4; i++)
        #pragma unroll
        for (int j = 0; j < 4; j++)
            #pragma unroll
            for (int r = 0; r < 4; r++) acc[i][j][r] = 0.f;

    for (int c0 = 0; c0 < CC; c0 += 32) {
        int c4 = (tid & 7) * 4;
        int rr = tid >> 3;
        #pragma unroll
        for (int oo = 0; oo < 128; oo += 32) {
            float4 v = *(const float4*)&Wo[(size_t)(ob + oo + rr) * CC + c0 + c4];
            unsigned* dst = &As[oo + rr][c4];
            dst[0] = f2tf32(v.x); dst[1] = f2tf32(v.y);
            dst[2] = f2tf32(v.z); dst[3] = f2tf32(v.w);
        }
        #pragma unroll
        for (int nn = 0; nn < 128; nn += 32) {
            float4 v = *(const float4*)&A[(size_t)(nb + nn + rr) * CC + c0 + c4];
            unsigned* dst = &Bs[nn + rr][c4];
            dst[0] = f2tf32(v.x); dst[1] = f2tf32(v.y);
            dst[2] = f2tf32(v.z); dst[3] = f2tf32(v.w);
        }
        __syncthreads();

        #pragma unroll
        for (int k8 = 0; k8 < 32; k8 += 8) {
            unsigned afr[4][4], bfr[4][2];
            #pragma unroll
            for (int mt = 0; mt < 4; mt++) {
                int row = wm * 64 + mt * 16;
                afr[mt][0] = As[row + g    ][k8 + t];
                afr[mt][1] = As[row + 8 + g][k8 + t];
                afr[mt][2] = As[row + g    ][k8 + 4 + t];
                afr[mt][3] = As[row + 8 + g][k8 + 4 + t];
            }
            #pragma unroll
            for (int nt = 0; nt < 4; nt++) {
                int col = wn * 32 + nt * 8;
                bfr[nt][0] = Bs[col + g][k8 + t];
                bfr[nt][1] = Bs[col + g][k8 + 4 + t];
            }
            #pragma unroll
            for (int mt = 0; mt < 4; mt++)
                #pragma unroll
                for (int nt = 0; nt < 4; nt++)
                    mma1688(acc[mt][nt], afr[mt], bfr[nt]);
        }
        __syncthreads();
    }

    const float* xp = x   + (size_t)b * CC * NQ;
    float*       op = out + (size_t)b * CC * NQ;
    #pragma unroll
    for (int mt = 0; mt < 4; mt++) {
        int o0 = ob + wm * 64 + mt * 16 + g;
        float bb0 = bo[o0], bb1 = bo[o0 + 8];
        #pragma unroll
        for (int nt = 0; nt < 4; nt++) {
            int n = nb + wn * 32 + nt * 8 + 2 * t;
            size_t base0 = (size_t)o0 * NQ + n;
            size_t base1 = (size_t)(o0 + 8) * NQ + n;
            float2 x0 = *(const float2*)&xp[base0];
            float2 x1 = *(const float2*)&xp[base1];
            float2 v0 = {acc[mt][nt][0] + bb0 + x0.x, acc[mt][nt][1] + bb0 + x0.y};
            float2 v1 = {acc[mt][nt][2] + bb1 + x1.x, acc[mt][nt][3] + bb1 + x1.y};
            *(float2*)&op[base0] = v0;
            *(float2*)&op[base1] = v1;
        }
    }
}

// ---------------------------------------------------------------------------
extern "C" void kernel_launch(void* const* d_in, const int* in_sizes, int n_in,
                              void* d_out, int out_size)
{
    const float* x    = (const float*)d_in[0];
    const int*   mask = (const int*)  d_in[1];
    const int*   aidx = (const int*)  d_in[2];
    const float* gsc  = (const float*)d_in[3];
    const float* gbi  = (const float*)d_in[4];
    const float* wq   = (const float*)d_in[5];
    const float* bq   = (const float*)d_in[6];
    const float* wk   = (const float*)d_in[7];
    const float* bk   = (const float*)d_in[8];
    const float* wv   = (const float*)d_in[9];
    const float* bv   = (const float*)d_in[10];
    const float* wo   = (const float*)d_in[11];
    const float* bo   = (const float*)d_in[12];
    float* out = (float*)d_out;

    gn_kernel<<<dim3(GROUPS, BB), 256>>>(x, gsc, gbi);

    gemm_qkv<<<dim3(NQ / 128, 6, BB), 256>>>(wq, bq, wk, bk, wv, bv);

    int total_warps = BB * NQ * HEADS;
    attn_kernel<<<total_warps * 32 / 256, 256>>>(mask, aidx);

    gemm_out<<<dim3(NQ / 128, CC / 128, BB), 256>>>(wo, bo, x, out);
}

// round 4
// speedup vs baseline: 2.5208x; 1.2799x over previous
#include <cuda_runtime.h>
#include <cuda_bf16.h>
#include <math.h>

#define BB     2
#define CC     256
#define NQ     4096
#define HEADS  4
#define DH     64
#define KK     64
#define GROUPS 32
#define CPG    8
#define EPS    1e-6f
#define LDC    36        // smem row pitch (floats) -> conflict-free mma frag loads

// Scratch (device globals; no allocation allowed)
__device__ float         g_h [BB*CC*NQ];   // groupnormed, [b][c][n]
__device__ float         g_qt[BB*NQ*CC];   // Q fp32, [b][n][c]  c = head*64 + d
__device__ __nv_bfloat16 g_kb[BB*NQ*CC];   // K bf16, [b][n][c]
__device__ __nv_bfloat16 g_vb[BB*NQ*CC];   // V bf16, [b][n][c]
__device__ float         g_at[BB*NQ*CC];   // attn out, [b][n][c]  c = d*HEADS + h

// ---------------------------------------------------------------------------
// tf32 helpers
// ---------------------------------------------------------------------------
__device__ __forceinline__ unsigned f2tf32(float f) {
    unsigned r;
    asm("cvt.rna.tf32.f32 %0, %1;" : "=r"(r) : "f"(f));
    return r;
}

__device__ __forceinline__ void mma1688(float d[4], const unsigned a[4],
                                        const unsigned b[2]) {
    asm("mma.sync.aligned.m16n8k8.row.col.f32.tf32.tf32.f32 "
        "{%0,%1,%2,%3}, {%4,%5,%6,%7}, {%8,%9}, {%0,%1,%2,%3};"
        : "+f"(d[0]), "+f"(d[1]), "+f"(d[2]), "+f"(d[3])
        : "r"(a[0]), "r"(a[1]), "r"(a[2]), "r"(a[3]),
          "r"(b[0]), "r"(b[1]));
}

// ---------------------------------------------------------------------------
// GroupNorm: grid (GROUPS, B), block 256
// ---------------------------------------------------------------------------
__global__ void gn_kernel(const float* __restrict__ x,
                          const float* __restrict__ scale,
                          const float* __restrict__ bias)
{
    const int g = blockIdx.x, b = blockIdx.y;
    const float* xp = x   + ((size_t)b*CC + g*CPG) * NQ;
    float*       hp = g_h + ((size_t)b*CC + g*CPG) * NQ;
    const int tid = threadIdx.x;
    const int NE  = CPG * NQ;

    float s = 0.f, s2 = 0.f;
    for (int i = tid; i < NE; i += 256) {
        float v = xp[i];
        s += v; s2 += v * v;
    }
    #pragma unroll
    for (int o = 16; o; o >>= 1) {
        s  += __shfl_xor_sync(~0u, s,  o);
        s2 += __shfl_xor_sync(~0u, s2, o);
    }
    __shared__ float shs[8], shs2[8];
    __shared__ float mean_s, rstd_s;
    int w = tid >> 5, l = tid & 31;
    if (l == 0) { shs[w] = s; shs2[w] = s2; }
    __syncthreads();
    if (tid == 0) {
        float a = 0.f, c = 0.f;
        #pragma unroll
        for (int i = 0; i < 8; i++) { a += shs[i]; c += shs2[i]; }
        float m   = a / NE;
        float var = c / NE - m * m;
        mean_s = m;
        rstd_s = rsqrtf(var + EPS);
    }
    __syncthreads();
    const float m = mean_s, r = rstd_s;
    for (int i = tid; i < NE; i += 256) {
        int ch = g * CPG + (i >> 12);
        hp[i] = (xp[i] - m) * r * scale[ch] + bias[ch];
    }
}

// ---------------------------------------------------------------------------
// Fused QKV GEMM (tf32 tensor core) — unchanged from round 3
// ---------------------------------------------------------------------------
__global__ void __launch_bounds__(256)
gemm_qkv(const float* __restrict__ wq, const float* __restrict__ bq,
         const float* __restrict__ wk, const float* __restrict__ bk,
         const float* __restrict__ wv, const float* __restrict__ bv)
{
    const int nb    = blockIdx.x * 128;
    const int which = blockIdx.y >> 1;
    const int ob    = (blockIdx.y & 1) * 128;
    const int b     = blockIdx.z;

    const float* W    = which == 0 ? wq : which == 1 ? wk : wv;
    const float* bias = which == 0 ? bq : which == 1 ? bk : bv;
    const float* X = g_h + (size_t)b * CC * NQ;   // [c][n]

    __shared__ unsigned As[128][LDC];   // [n][c] tf32
    __shared__ unsigned Bs[128][LDC];   // [o][c] tf32

    const int tid  = threadIdx.x;
    const int wid  = tid >> 5, lane = tid & 31;
    const int wm   = wid & 1,  wn   = wid >> 1;
    const int g    = lane >> 2, t   = lane & 3;

    float acc[4][4][4];
    #pragma unroll
    for (int i = 0; i < 4; i++)
        #pragma unroll
        for (int j = 0; j < 4; j++)
            #pragma unroll
            for (int r = 0; r < 4; r++) acc[i][j][r] = 0.f;

    for (int c0 = 0; c0 < CC; c0 += 32) {
        #pragma unroll
        for (int cc = 0; cc < 32; cc += 8) {
            #pragma unroll
            for (int nn = 0; nn < 128; nn += 32) {
                float v = X[(size_t)(c0 + cc + wid) * NQ + nb + nn + lane];
                As[nn + lane][cc + wid] = f2tf32(v);
            }
        }
        {
            int c4 = (tid & 7) * 4;
            int o  = tid >> 3;
            #pragma unroll
            for (int oo = 0; oo < 128; oo += 32) {
                float4 v = *(const float4*)&W[(size_t)(ob + oo + o) * CC + c0 + c4];
                unsigned* dst = &Bs[oo + o][c4];
                dst[0] = f2tf32(v.x); dst[1] = f2tf32(v.y);
                dst[2] = f2tf32(v.z); dst[3] = f2tf32(v.w);
            }
        }
        __syncthreads();

        #pragma unroll
        for (int k8 = 0; k8 < 32; k8 += 8) {
            unsigned afr[4][4], bfr[4][2];
            #pragma unroll
            for (int mt = 0; mt < 4; mt++) {
                int row = wm * 64 + mt * 16;
                afr[mt][0] = As[row + g    ][k8 + t];
                afr[mt][1] = As[row + 8 + g][k8 + t];
                afr[mt][2] = As[row + g    ][k8 + 4 + t];
                afr[mt][3] = As[row + 8 + g][k8 + 4 + t];
            }
            #pragma unroll
            for (int nt = 0; nt < 4; nt++) {
                int col = wn * 32 + nt * 8;
                bfr[nt][0] = Bs[col + g][k8 + t];
                bfr[nt][1] = Bs[col + g][k8 + 4 + t];
            }
            #pragma unroll
            for (int mt = 0; mt < 4; mt++)
                #pragma unroll
                for (int nt = 0; nt < 4; nt++)
                    mma1688(acc[mt][nt], afr[mt], bfr[nt]);
        }
        __syncthreads();
    }

    if (which == 0) {
        float* O = g_qt + (size_t)b * NQ * CC;
        #pragma unroll
        for (int nt = 0; nt < 4; nt++) {
            int o = ob + wn * 32 + nt * 8 + 2 * t;
            float bb0 = bias[o], bb1 = bias[o + 1];
            #pragma unroll
            for (int mt = 0; mt < 4; mt++) {
                int n0 = nb + wm * 64 + mt * 16 + g;
                float2 v0 = {acc[mt][nt][0] + bb0, acc[mt][nt][1] + bb1};
                float2 v1 = {acc[mt][nt][2] + bb0, acc[mt][nt][3] + bb1};
                *(float2*)&O[(size_t)n0 * CC + o]       = v0;
                *(float2*)&O[(size_t)(n0 + 8) * CC + o] = v1;
            }
        }
    } else {
        __nv_bfloat16* O = (which == 1 ? g_kb : g_vb) + (size_t)b * NQ * CC;
        #pragma unroll
        for (int nt = 0; nt < 4; nt++) {
            int o = ob + wn * 32 + nt * 8 + 2 * t;
            float bb0 = bias[o], bb1 = bias[o + 1];
            #pragma unroll
            for (int mt = 0; mt < 4; mt++) {
                int n0 = nb + wm * 64 + mt * 16 + g;
                __nv_bfloat162 v0 = {__float2bfloat16_rn(acc[mt][nt][0] + bb0),
                                     __float2bfloat16_rn(acc[mt][nt][1] + bb1)};
                __nv_bfloat162 v1 = {__float2bfloat16_rn(acc[mt][nt][2] + bb0),
                                     __float2bfloat16_rn(acc[mt][nt][3] + bb1)};
                *(__nv_bfloat162*)&O[(size_t)n0 * CC + o]       = v0;
                *(__nv_bfloat162*)&O[(size_t)(n0 + 8) * CC + o] = v1;
            }
        }
    }
}

// ---------------------------------------------------------------------------
// Sparse attention v2: ONE warp per (b, n), ALL 4 heads together.
// Per key: one 512B row load (float4/lane = 8 bf16 ch), 3-shuffle segmented
// reduce (heads = 8-lane groups), 4-shuffle distribute. Lane l owns logits
// for keys l and l+32 (all heads). Masked keys skipped warp-uniformly.
// ---------------------------------------------------------------------------
__device__ __forceinline__ void unpack8(float4 u, float* f) {
    const __nv_bfloat162* p = (const __nv_bfloat162*)&u;
    float2 a = __bfloat1622float2(p[0]);
    float2 b = __bfloat1622float2(p[1]);
    float2 c = __bfloat1622float2(p[2]);
    float2 d = __bfloat1622float2(p[3]);
    f[0]=a.x; f[1]=a.y; f[2]=b.x; f[3]=b.y;
    f[4]=c.x; f[5]=c.y; f[6]=d.x; f[7]=d.y;
}

__global__ void __launch_bounds__(256)
attn_kernel(const int* __restrict__ mask, const int* __restrict__ aidx)
{
    const int gw = (blockIdx.x * blockDim.x + threadIdx.x) >> 5;
    const int l  = threadIdx.x & 31;
    const int n  = gw & (NQ - 1);
    const int b  = gw >> 12;

    const float*         qp = g_qt + ((size_t)b * NQ + n) * CC;
    const __nv_bfloat16* Kb = g_kb + (size_t)b * NQ * CC;
    const __nv_bfloat16* Vb = g_vb + (size_t)b * NQ * CC;

    // q channels 8l..8l+7 (head = l>>3)
    float qv[8];
    {
        float4 a = *(const float4*)&qp[8 * l];
        float4 c = *(const float4*)&qp[8 * l + 4];
        qv[0]=a.x; qv[1]=a.y; qv[2]=a.z; qv[3]=a.w;
        qv[4]=c.x; qv[5]=c.y; qv[6]=c.z; qv[7]=c.w;
    }

    const int idx0 = aidx[n * KK + l];
    const int idx1 = aidx[n * KK + l + 32];
    const int m0   = mask[n * KK + l];
    const int m1   = mask[n * KK + l + 32];

    // lane l holds logits for key l (lg0) and key l+32 (lg1), all 4 heads
    float lg0[4] = {-INFINITY, -INFINITY, -INFINITY, -INFINITY};
    float lg1[4] = {-INFINITY, -INFINITY, -INFINITY, -INFINITY};

    // ---- K pass, keys 0..31 ----
    #pragma unroll 4
    for (int kk = 0; kk < 32; kk++) {
        int mk = __shfl_sync(~0u, m0, kk);
        if (!mk) continue;
        int idx = __shfl_sync(~0u, idx0, kk);
        float kf[8];
        unpack8(((const float4*)(Kb + (size_t)idx * CC))[l], kf);
        float p = 0.f;
        #pragma unroll
        for (int j = 0; j < 8; j++) p += qv[j] * kf[j];
        p += __shfl_xor_sync(~0u, p, 4);
        p += __shfl_xor_sync(~0u, p, 2);
        p += __shfl_xor_sync(~0u, p, 1);
        float v0 = __shfl_sync(~0u, p, 0);
        float v1 = __shfl_sync(~0u, p, 8);
        float v2 = __shfl_sync(~0u, p, 16);
        float v3 = __shfl_sync(~0u, p, 24);
        if (kk == l) { lg0[0]=v0; lg0[1]=v1; lg0[2]=v2; lg0[3]=v3; }
    }
    // ---- K pass, keys 32..63 ----
    #pragma unroll 4
    for (int kk = 0; kk < 32; kk++) {
        int mk = __shfl_sync(~0u, m1, kk);
        if (!mk) continue;
        int idx = __shfl_sync(~0u, idx1, kk);
        float kf[8];
        unpack8(((const float4*)(Kb + (size_t)idx * CC))[l], kf);
        float p = 0.f;
        #pragma unroll
        for (int j = 0; j < 8; j++) p += qv[j] * kf[j];
        p += __shfl_xor_sync(~0u, p, 4);
        p += __shfl_xor_sync(~0u, p, 2);
        p += __shfl_xor_sync(~0u, p, 1);
        float v0 = __shfl_sync(~0u, p, 0);
        float v1 = __shfl_sync(~0u, p, 8);
        float v2 = __shfl_sync(~0u, p, 16);
        float v3 = __shfl_sync(~0u, p, 24);
        if (kk == l) { lg1[0]=v0; lg1[1]=v1; lg1[2]=v2; lg1[3]=v3; }
    }

    // ---- softmax per head (over 64 keys distributed 2-per-lane) ----
    float w0[4], w1[4];
    #pragma unroll
    for (int h = 0; h < 4; h++) {
        float mx = fmaxf(lg0[h], lg1[h]);
        #pragma unroll
        for (int o = 16; o; o >>= 1)
            mx = fmaxf(mx, __shfl_xor_sync(~0u, mx, o));
        float e0 = __expf(lg0[h] - mx);
        float e1 = __expf(lg1[h] - mx);
        float s = e0 + e1;
        #pragma unroll
        for (int o = 16; o; o >>= 1) s += __shfl_xor_sync(~0u, s, o);
        float inv = 1.f / s;
        w0[h] = e0 * inv;
        w1[h] = e1 * inv;
    }

    // ---- V pass ----
    float acc[8] = {0.f,0.f,0.f,0.f,0.f,0.f,0.f,0.f};
    const int hsel = l >> 3;

    #pragma unroll 4
    for (int kk = 0; kk < 32; kk++) {
        int mk = __shfl_sync(~0u, m0, kk);
        if (!mk) continue;
        int idx = __shfl_sync(~0u, idx0, kk);
        float a0 = __shfl_sync(~0u, w0[0], kk);
        float a1 = __shfl_sync(~0u, w0[1], kk);
        float a2 = __shfl_sync(~0u, w0[2], kk);
        float a3 = __shfl_sync(~0u, w0[3], kk);
        float myw = hsel == 0 ? a0 : hsel == 1 ? a1 : hsel == 2 ? a2 : a3;
        float vf[8];
        unpack8(((const float4*)(Vb + (size_t)idx * CC))[l], vf);
        #pragma unroll
        for (int j = 0; j < 8; j++) acc[j] += myw * vf[j];
    }
    #pragma unroll 4
    for (int kk = 0; kk < 32; kk++) {
        int mk = __shfl_sync(~0u, m1, kk);
        if (!mk) continue;
        int idx = __shfl_sync(~0u, idx1, kk);
        float a0 = __shfl_sync(~0u, w1[0], kk);
        float a1 = __shfl_sync(~0u, w1[1], kk);
        float a2 = __shfl_sync(~0u, w1[2], kk);
        float a3 = __shfl_sync(~0u, w1[3], kk);
        float myw = hsel == 0 ? a0 : hsel == 1 ? a1 : hsel == 2 ? a2 : a3;
        float vf[8];
        unpack8(((const float4*)(Vb + (size_t)idx * CC))[l], vf);
        #pragma unroll
        for (int j = 0; j < 8; j++) acc[j] += myw * vf[j];
    }

    // ---- store, interleaved channel order c_out = d*HEADS + h ----
    float* at = g_at + ((size_t)b * NQ + n) * CC;
    #pragma unroll
    for (int j = 0; j < 8; j++) {
        int c = 8 * l + j;          // c = 64*h + d
        int d = c & 63;
        at[d * HEADS + hsel] = acc[j];
    }
}

// ---------------------------------------------------------------------------
// Output projection + residual (tf32 tensor core) — unchanged from round 3
// ---------------------------------------------------------------------------
__global__ void __launch_bounds__(256)
gemm_out(const float* __restrict__ Wo, const float* __restrict__ bo,
         const float* __restrict__ x,  float* __restrict__ out)
{
    const int nb = blockIdx.x * 128, ob = blockIdx.y * 128, b = blockIdx.z;
    const float* A = g_at + (size_t)b * NQ * CC;   // [n][c]

    __shared__ unsigned As[128][LDC];   // [o][c] tf32
    __shared__ unsigned Bs[128][LDC];   // [n][c] tf32

    const int tid  = threadIdx.x;
    const int wid  = tid >> 5, lane = tid & 31;
    const int wm   = wid & 1,  wn   = wid >> 1;
    const int g    = lane >> 2, t   = lane & 3;

    float acc[4][4][4];
    #pragma unroll
    for (int i = 0; i < 4; i++)
        #pragma unroll
        for (int j = 0; j < 4; j++)
            #pragma unroll
            for (int r = 0; r < 4; r++) acc[i][j][r] = 0.f;

    for (int c0 = 0; c0 < CC; c0 += 32) {
        int c4 = (tid & 7) * 4;
        int rr = tid >> 3;
        #pragma unroll
        for (int oo = 0; oo < 128; oo += 32) {
            float4 v = *(const float4*)&Wo[(size_t)(ob + oo + rr) * CC + c0 + c4];
            unsigned* dst = &As[oo + rr][c4];
            dst[0] = f2tf32(v.x); dst[1] = f2tf32(v.y);
            dst[2] = f2tf32(v.z); dst[3] = f2tf32(v.w);
        }
        #pragma unroll
        for (int nn = 0; nn < 128; nn += 32) {
            float4 v = *(const float4*)&A[(size_t)(nb + nn + rr) * CC + c0 + c4];
            unsigned* dst = &Bs[nn + rr][c4];
            dst[0] = f2tf32(v.x); dst[1] = f2tf32(v.y);
            dst[2] = f2tf32(v.z); dst[3] = f2tf32(v.w);
        }
        __syncthreads();

        #pragma unroll
        for (int k8 = 0; k8 < 32; k8 += 8) {
            unsigned afr[4][4], bfr[4][2];
            #pragma unroll
            for (int mt = 0; mt < 4; mt++) {
                int row = wm * 64 + mt * 16;
                afr[mt][0] = As[row + g    ][k8 + t];
                afr[mt][1] = As[row + 8 + g][k8 + t];
                afr[mt][2] = As[row + g    ][k8 + 4 + t];
                afr[mt][3] = As[row + 8 + g][k8 + 4 + t];
            }
            #pragma unroll
            for (int nt = 0; nt < 4; nt++) {
                int col = wn * 32 + nt * 8;
                bfr[nt][0] = Bs[col + g][k8 + t];
                bfr[nt][1] = Bs[col + g][k8 + 4 + t];
            }
            #pragma unroll
            for (int mt = 0; mt < 4; mt++)
                #pragma unroll
                for (int nt = 0; nt < 4; nt++)
                    mma1688(acc[mt][nt], afr[mt], bfr[nt]);
        }
        __syncthreads();
    }

    const float* xp = x   + (size_t)b * CC * NQ;
    float*       op = out + (size_t)b * CC * NQ;
    #pragma unroll
    for (int mt = 0; mt < 4; mt++) {
        int o0 = ob + wm * 64 + mt * 16 + g;
        float bb0 = bo[o0], bb1 = bo[o0 + 8];
        #pragma unroll
        for (int nt = 0; nt < 4; nt++) {
            int n = nb + wn * 32 + nt * 8 + 2 * t;
            size_t base0 = (size_t)o0 * NQ + n;
            size_t base1 = (size_t)(o0 + 8) * NQ + n;
            float2 x0 = *(const float2*)&xp[base0];
            float2 x1 = *(const float2*)&xp[base1];
            float2 v0 = {acc[mt][nt][0] + bb0 + x0.x, acc[mt][nt][1] + bb0 + x0.y};
            float2 v1 = {acc[mt][nt][2] + bb1 + x1.x, acc[mt][nt][3] + bb1 + x1.y};
            *(float2*)&op[base0] = v0;
            *(float2*)&op[base1] = v1;
        }
    }
}

// ---------------------------------------------------------------------------
extern "C" void kernel_launch(void* const* d_in, const int* in_sizes, int n_in,
                              void* d_out, int out_size)
{
    const float* x    = (const float*)d_in[0];
    const int*   mask = (const int*)  d_in[1];
    const int*   aidx = (const int*)  d_in[2];
    const float* gsc  = (const float*)d_in[3];
    const float* gbi  = (const float*)d_in[4];
    const float* wq   = (const float*)d_in[5];
    const float* bq   = (const float*)d_in[6];
    const float* wk   = (const float*)d_in[7];
    const float* bk   = (const float*)d_in[8];
    const float* wv   = (const float*)d_in[9];
    const float* bv   = (const float*)d_in[10];
    const float* wo   = (const float*)d_in[11];
    const float* bo   = (const float*)d_in[12];
    float* out = (float*)d_out;

    gn_kernel<<<dim3(GROUPS, BB), 256>>>(x, gsc, gbi);

    gemm_qkv<<<dim3(NQ / 128, 6, BB), 256>>>(wq, bq, wk, bk, wv, bv);

    // one warp per (b, n): B*NQ warps
    int total_warps = BB * NQ;
    attn_kernel<<<total_warps * 32 / 256, 256>>>(mask, aidx);

    gemm_out<<<dim3(NQ / 128, CC / 128, BB), 256>>>(wo, bo, x, out);
}

// round 5
// speedup vs baseline: 2.7351x; 1.0850x over previous
#include <cuda_runtime.h>
#include <cuda_bf16.h>
#include <math.h>

#define BB     2
#define CC     256
#define NQ     4096
#define HEADS  4
#define DH     64
#define KK     64
#define GROUPS 32
#define CPG    8
#define EPS    1e-6f

#define PAD_A  136      // [c][n] layout pad: 136 mod 32 = 8 -> 8t+g conflict-free
#define PAD_B  36       // [row][c] layout pad: 36 mod 32 = 4 -> 4g+t conflict-free

// Scratch (device globals; no allocation allowed)
__device__ float         g_h [BB*CC*NQ];   // groupnormed, [b][c][n]
__device__ float         g_qt[BB*NQ*CC];   // Q fp32, [b][n][c]  c = head*64 + d
__device__ __nv_bfloat16 g_kb[BB*NQ*CC];   // K bf16, [b][n][c]
__device__ __nv_bfloat16 g_vb[BB*NQ*CC];   // V bf16, [b][n][c]
__device__ float         g_at[BB*NQ*CC];   // attn out, [b][n][c]  c = d*HEADS + h

// ---------------------------------------------------------------------------
// helpers
// ---------------------------------------------------------------------------
__device__ __forceinline__ void mma1688(float d[4], const unsigned a[4],
                                        const unsigned b[2]) {
    asm("mma.sync.aligned.m16n8k8.row.col.f32.tf32.tf32.f32 "
        "{%0,%1,%2,%3}, {%4,%5,%6,%7}, {%8,%9}, {%0,%1,%2,%3};"
        : "+f"(d[0]), "+f"(d[1]), "+f"(d[2]), "+f"(d[3])
        : "r"(a[0]), "r"(a[1]), "r"(a[2]), "r"(a[3]),
          "r"(b[0]), "r"(b[1]));
}

__device__ __forceinline__ void cp16(unsigned dst, const void* src) {
    asm volatile("cp.async.cg.shared.global [%0], [%1], 16;"
                 :: "r"(dst), "l"(src));
}
#define CP_COMMIT() asm volatile("cp.async.commit_group;")
#define CP_WAIT(n)  asm volatile("cp.async.wait_group %0;" :: "n"(n))

// ---------------------------------------------------------------------------
// GroupNorm: grid (GROUPS, B), block 256
// ---------------------------------------------------------------------------
__global__ void gn_kernel(const float* __restrict__ x,
                          const float* __restrict__ scale,
                          const float* __restrict__ bias)
{
    const int g = blockIdx.x, b = blockIdx.y;
    const float* xp = x   + ((size_t)b*CC + g*CPG) * NQ;
    float*       hp = g_h + ((size_t)b*CC + g*CPG) * NQ;
    const int tid = threadIdx.x;
    const int NE  = CPG * NQ;

    float s = 0.f, s2 = 0.f;
    for (int i = tid; i < NE; i += 256) {
        float v = xp[i];
        s += v; s2 += v * v;
    }
    #pragma unroll
    for (int o = 16; o; o >>= 1) {
        s  += __shfl_xor_sync(~0u, s,  o);
        s2 += __shfl_xor_sync(~0u, s2, o);
    }
    __shared__ float shs[8], shs2[8];
    __shared__ float mean_s, rstd_s;
    int w = tid >> 5, l = tid & 31;
    if (l == 0) { shs[w] = s; shs2[w] = s2; }
    __syncthreads();
    if (tid == 0) {
        float a = 0.f, c = 0.f;
        #pragma unroll
        for (int i = 0; i < 8; i++) { a += shs[i]; c += shs2[i]; }
        float m   = a / NE;
        float var = c / NE - m * m;
        mean_s = m;
        rstd_s = rsqrtf(var + EPS);
    }
    __syncthreads();
    const float m = mean_s, r = rstd_s;
    for (int i = tid; i < NE; i += 256) {
        int ch = g * CPG + (i >> 12);
        hp[i] = (xp[i] - m) * r * scale[ch] + bias[ch];
    }
}

// ---------------------------------------------------------------------------
// Fused QKV GEMM (tf32 MMA, cp.async double-buffered):
// O[b][n][o] = sum_c W[o][c] * g_h[b][c][n] + bias[o]
// Block 128(n=M) x 128(o=N), k-step 32. smem: As[2][32][PAD_A] ([c][n]),
// Bs[2][128][PAD_B] ([o][c]). Raw fp32 bits fed to tf32 MMA (RZ truncation).
// grid (NQ/128, 6, B): y>>1 = which, (y&1)*128 = o-block.
// ---------------------------------------------------------------------------
#define QKV_SMEM ((2*32*PAD_A + 2*128*PAD_B) * 4)

__global__ void __launch_bounds__(256)
gemm_qkv(const float* __restrict__ wq, const float* __restrict__ bq,
         const float* __restrict__ wk, const float* __restrict__ bk,
         const float* __restrict__ wv, const float* __restrict__ bv)
{
    extern __shared__ unsigned smem_dyn[];
    unsigned* As = smem_dyn;                 // [2][32][PAD_A]
    unsigned* Bs = smem_dyn + 2*32*PAD_A;    // [2][128][PAD_B]

    const int nb    = blockIdx.x * 128;
    const int which = blockIdx.y >> 1;
    const int ob    = (blockIdx.y & 1) * 128;
    const int b     = blockIdx.z;

    const float* W    = which == 0 ? wq : which == 1 ? wk : wv;
    const float* bias = which == 0 ? bq : which == 1 ? bk : bv;
    const float* X = g_h + (size_t)b * CC * NQ;   // [c][n]

    const int tid  = threadIdx.x;
    const int wid  = tid >> 5, lane = tid & 31;
    const int wm   = wid & 1,  wn   = wid >> 1;
    const int g    = lane >> 2, t   = lane & 3;

    const unsigned as_base = (unsigned)__cvta_generic_to_shared(As);
    const unsigned bs_base = (unsigned)__cvta_generic_to_shared(Bs);

    // A chunks: c = ch>>5, seg = ch&31 (32 float4 per c-row)
    const int a_c = tid >> 5, a_seg = tid & 31;
    // B chunks: o = ch>>3, seg = ch&7 (8 float4 per o-row)
    const int b_o = tid >> 3, b_seg = tid & 7;

    #define LOAD_STAGE(s, c0)                                                  \
    {                                                                          \
        _Pragma("unroll")                                                      \
        for (int j = 0; j < 4; j++) {                                          \
            int c = a_c + j * 8;                                               \
            cp16(as_base + (((s)*32 + c) * PAD_A + a_seg * 4) * 4,             \
                 X + (size_t)((c0) + c) * NQ + nb + a_seg * 4);                \
        }                                                                      \
        _Pragma("unroll")                                                      \
        for (int j = 0; j < 4; j++) {                                          \
            int o = b_o + j * 32;                                              \
            cp16(bs_base + (((s)*128 + o) * PAD_B + b_seg * 4) * 4,            \
                 W + (size_t)(ob + o) * CC + (c0) + b_seg * 4);                \
        }                                                                      \
        CP_COMMIT();                                                           \
    }

    float acc[4][4][4];
    #pragma unroll
    for (int i = 0; i < 4; i++)
        #pragma unroll
        for (int j = 0; j < 4; j++)
            #pragma unroll
            for (int r = 0; r < 4; r++) acc[i][j][r] = 0.f;

    LOAD_STAGE(0, 0);

    #pragma unroll
    for (int ks = 0; ks < 8; ks++) {
        const int cur = ks & 1;
        if (ks < 7) {
            LOAD_STAGE(1 - cur, (ks + 1) * 32);
            CP_WAIT(1);
        } else {
            CP_WAIT(0);
        }
        __syncthreads();

        #pragma unroll
        for (int k8 = 0; k8 < 32; k8 += 8) {
            unsigned afr[4][4], bfr[4][2];
            #pragma unroll
            for (int mt = 0; mt < 4; mt++) {
                int row = wm * 64 + mt * 16;
                afr[mt][0] = As[(cur*32 + k8 + t    ) * PAD_A + row + g    ];
                afr[mt][1] = As[(cur*32 + k8 + t    ) * PAD_A + row + 8 + g];
                afr[mt][2] = As[(cur*32 + k8 + 4 + t) * PAD_A + row + g    ];
                afr[mt][3] = As[(cur*32 + k8 + 4 + t) * PAD_A + row + 8 + g];
            }
            #pragma unroll
            for (int nt = 0; nt < 4; nt++) {
                int col = wn * 32 + nt * 8;
                bfr[nt][0] = Bs[(cur*128 + col + g) * PAD_B + k8 + t    ];
                bfr[nt][1] = Bs[(cur*128 + col + g) * PAD_B + k8 + 4 + t];
            }
            #pragma unroll
            for (int mt = 0; mt < 4; mt++)
                #pragma unroll
                for (int nt = 0; nt < 4; nt++)
                    mma1688(acc[mt][nt], afr[mt], bfr[nt]);
        }
        __syncthreads();
    }
    #undef LOAD_STAGE

    if (which == 0) {
        float* O = g_qt + (size_t)b * NQ * CC;
        #pragma unroll
        for (int nt = 0; nt < 4; nt++) {
            int o = ob + wn * 32 + nt * 8 + 2 * t;
            float bb0 = bias[o], bb1 = bias[o + 1];
            #pragma unroll
            for (int mt = 0; mt < 4; mt++) {
                int n0 = nb + wm * 64 + mt * 16 + g;
                float2 v0 = {acc[mt][nt][0] + bb0, acc[mt][nt][1] + bb1};
                float2 v1 = {acc[mt][nt][2] + bb0, acc[mt][nt][3] + bb1};
                *(float2*)&O[(size_t)n0 * CC + o]       = v0;
                *(float2*)&O[(size_t)(n0 + 8) * CC + o] = v1;
            }
        }
    } else {
        __nv_bfloat16* O = (which == 1 ? g_kb : g_vb) + (size_t)b * NQ * CC;
        #pragma unroll
        for (int nt = 0; nt < 4; nt++) {
            int o = ob + wn * 32 + nt * 8 + 2 * t;
            float bb0 = bias[o], bb1 = bias[o + 1];
            #pragma unroll
            for (int mt = 0; mt < 4; mt++) {
                int n0 = nb + wm * 64 + mt * 16 + g;
                __nv_bfloat162 v0 = {__float2bfloat16_rn(acc[mt][nt][0] + bb0),
                                     __float2bfloat16_rn(acc[mt][nt][1] + bb1)};
                __nv_bfloat162 v1 = {__float2bfloat16_rn(acc[mt][nt][2] + bb0),
                                     __float2bfloat16_rn(acc[mt][nt][3] + bb1)};
                *(__nv_bfloat162*)&O[(size_t)n0 * CC + o]       = v0;
                *(__nv_bfloat162*)&O[(size_t)(n0 + 8) * CC + o] = v1;
            }
        }
    }
}

// ---------------------------------------------------------------------------
// Sparse attention: one warp per (b, n), all 4 heads (unchanged from round 4)
// ---------------------------------------------------------------------------
__device__ __forceinline__ void unpack8(float4 u, float* f) {
    const __nv_bfloat162* p = (const __nv_bfloat162*)&u;
    float2 a = __bfloat1622float2(p[0]);
    float2 b = __bfloat1622float2(p[1]);
    float2 c = __bfloat1622float2(p[2]);
    float2 d = __bfloat1622float2(p[3]);
    f[0]=a.x; f[1]=a.y; f[2]=b.x; f[3]=b.y;
    f[4]=c.x; f[5]=c.y; f[6]=d.x; f[7]=d.y;
}

__global__ void __launch_bounds__(256)
attn_kernel(const int* __restrict__ mask, const int* __restrict__ aidx)
{
    const int gw = (blockIdx.x * blockDim.x + threadIdx.x) >> 5;
    const int l  = threadIdx.x & 31;
    const int n  = gw & (NQ - 1);
    const int b  = gw >> 12;

    const float*         qp = g_qt + ((size_t)b * NQ + n) * CC;
    const __nv_bfloat16* Kb = g_kb + (size_t)b * NQ * CC;
    const __nv_bfloat16* Vb = g_vb + (size_t)b * NQ * CC;

    float qv[8];
    {
        float4 a = *(const float4*)&qp[8 * l];
        float4 c = *(const float4*)&qp[8 * l + 4];
        qv[0]=a.x; qv[1]=a.y; qv[2]=a.z; qv[3]=a.w;
        qv[4]=c.x; qv[5]=c.y; qv[6]=c.z; qv[7]=c.w;
    }

    const int idx0 = aidx[n * KK + l];
    const int idx1 = aidx[n * KK + l + 32];
    const int m0   = mask[n * KK + l];
    const int m1   = mask[n * KK + l + 32];

    float lg0[4] = {-INFINITY, -INFINITY, -INFINITY, -INFINITY};
    float lg1[4] = {-INFINITY, -INFINITY, -INFINITY, -INFINITY};

    #pragma unroll 4
    for (int kk = 0; kk < 32; kk++) {
        int mk = __shfl_sync(~0u, m0, kk);
        if (!mk) continue;
        int idx = __shfl_sync(~0u, idx0, kk);
        float kf[8];
        unpack8(((const float4*)(Kb + (size_t)idx * CC))[l], kf);
        float p = 0.f;
        #pragma unroll
        for (int j = 0; j < 8; j++) p += qv[j] * kf[j];
        p += __shfl_xor_sync(~0u, p, 4);
        p += __shfl_xor_sync(~0u, p, 2);
        p += __shfl_xor_sync(~0u, p, 1);
        float v0 = __shfl_sync(~0u, p, 0);
        float v1 = __shfl_sync(~0u, p, 8);
        float v2 = __shfl_sync(~0u, p, 16);
        float v3 = __shfl_sync(~0u, p, 24);
        if (kk == l) { lg0[0]=v0; lg0[1]=v1; lg0[2]=v2; lg0[3]=v3; }
    }
    #pragma unroll 4
    for (int kk = 0; kk < 32; kk++) {
        int mk = __shfl_sync(~0u, m1, kk);
        if (!mk) continue;
        int idx = __shfl_sync(~0u, idx1, kk);
        float kf[8];
        unpack8(((const float4*)(Kb + (size_t)idx * CC))[l], kf);
        float p = 0.f;
        #pragma unroll
        for (int j = 0; j < 8; j++) p += qv[j] * kf[j];
        p += __shfl_xor_sync(~0u, p, 4);
        p += __shfl_xor_sync(~0u, p, 2);
        p += __shfl_xor_sync(~0u, p, 1);
        float v0 = __shfl_sync(~0u, p, 0);
        float v1 = __shfl_sync(~0u, p, 8);
        float v2 = __shfl_sync(~0u, p, 16);
        float v3 = __shfl_sync(~0u, p, 24);
        if (kk == l) { lg1[0]=v0; lg1[1]=v1; lg1[2]=v2; lg1[3]=v3; }
    }

    float w0[4], w1[4];
    #pragma unroll
    for (int h = 0; h < 4; h++) {
        float mx = fmaxf(lg0[h], lg1[h]);
        #pragma unroll
        for (int o = 16; o; o >>= 1)
            mx = fmaxf(mx, __shfl_xor_sync(~0u, mx, o));
        float e0 = __expf(lg0[h] - mx);
        float e1 = __expf(lg1[h] - mx);
        float s = e0 + e1;
        #pragma unroll
        for (int o = 16; o; o >>= 1) s += __shfl_xor_sync(~0u, s, o);
        float inv = 1.f / s;
        w0[h] = e0 * inv;
        w1[h] = e1 * inv;
    }

    float acc[8] = {0.f,0.f,0.f,0.f,0.f,0.f,0.f,0.f};
    const int hsel = l >> 3;

    #pragma unroll 4
    for (int kk = 0; kk < 32; kk++) {
        int mk = __shfl_sync(~0u, m0, kk);
        if (!mk) continue;
        int idx = __shfl_sync(~0u, idx0, kk);
        float a0 = __shfl_sync(~0u, w0[0], kk);
        float a1 = __shfl_sync(~0u, w0[1], kk);
        float a2 = __shfl_sync(~0u, w0[2], kk);
        float a3 = __shfl_sync(~0u, w0[3], kk);
        float myw = hsel == 0 ? a0 : hsel == 1 ? a1 : hsel == 2 ? a2 : a3;
        float vf[8];
        unpack8(((const float4*)(Vb + (size_t)idx * CC))[l], vf);
        #pragma unroll
        for (int j = 0; j < 8; j++) acc[j] += myw * vf[j];
    }
    #pragma unroll 4
    for (int kk = 0; kk < 32; kk++) {
        int mk = __shfl_sync(~0u, m1, kk);
        if (!mk) continue;
        int idx = __shfl_sync(~0u, idx1, kk);
        float a0 = __shfl_sync(~0u, w1[0], kk);
        float a1 = __shfl_sync(~0u, w1[1], kk);
        float a2 = __shfl_sync(~0u, w1[2], kk);
        float a3 = __shfl_sync(~0u, w1[3], kk);
        float myw = hsel == 0 ? a0 : hsel == 1 ? a1 : hsel == 2 ? a2 : a3;
        float vf[8];
        unpack8(((const float4*)(Vb + (size_t)idx * CC))[l], vf);
        #pragma unroll
        for (int j = 0; j < 8; j++) acc[j] += myw * vf[j];
    }

    float* at = g_at + ((size_t)b * NQ + n) * CC;
    #pragma unroll
    for (int j = 0; j < 8; j++) {
        int c = 8 * l + j;
        int d = c & 63;
        at[d * HEADS + hsel] = acc[j];
    }
}

// ---------------------------------------------------------------------------
// Output projection + residual (tf32 MMA, cp.async double-buffered):
// out[b][o][n] = x[b][o][n] + sum_c Wo[o][c] * g_at[b][n][c] + bo[o]
// Block 128(o=M) x 128(n=N). smem: As[2][128][PAD_B] (Wo), Bs[2][128][PAD_B].
// ---------------------------------------------------------------------------
#define OUT_SMEM ((2*128*PAD_B * 2) * 4)

__global__ void __launch_bounds__(256)
gemm_out(const float* __restrict__ Wo, const float* __restrict__ bo,
         const float* __restrict__ x,  float* __restrict__ out)
{
    extern __shared__ unsigned smem_dyn[];
    unsigned* As = smem_dyn;                   // [2][128][PAD_B]  Wo [o][c]
    unsigned* Bs = smem_dyn + 2*128*PAD_B;     // [2][128][PAD_B]  at [n][c]

    const int nb = blockIdx.x * 128, ob = blockIdx.y * 128, b = blockIdx.z;
    const float* A = g_at + (size_t)b * NQ * CC;   // [n][c]

    const int tid  = threadIdx.x;
    const int wid  = tid >> 5, lane = tid & 31;
    const int wm   = wid & 1,  wn   = wid >> 1;
    const int g    = lane >> 2, t   = lane & 3;

    const unsigned as_base = (unsigned)__cvta_generic_to_shared(As);
    const unsigned bs_base = (unsigned)__cvta_generic_to_shared(Bs);

    const int r_o = tid >> 3, r_seg = tid & 7;

    #define LOAD_STAGE(s, c0)                                                  \
    {                                                                          \
        _Pragma("unroll")                                                      \
        for (int j = 0; j < 4; j++) {                                          \
            int o = r_o + j * 32;                                              \
            cp16(as_base + (((s)*128 + o) * PAD_B + r_seg * 4) * 4,            \
                 Wo + (size_t)(ob + o) * CC + (c0) + r_seg * 4);               \
        }                                                                      \
        _Pragma("unroll")                                                      \
        for (int j = 0; j < 4; j++) {                                          \
            int n = r_o + j * 32;                                              \
            cp16(bs_base + (((s)*128 + n) * PAD_B + r_seg * 4) * 4,            \
                 A + (size_t)(nb + n) * CC + (c0) + r_seg * 4);                \
        }                                                                      \
        CP_COMMIT();                                                           \
    }

    float acc[4][4][4];
    #pragma unroll
    for (int i = 0; i < 4; i++)
        #pragma unroll
        for (int j = 0; j < 4; j++)
            #pragma unroll
            for (int r = 0; r < 4; r++) acc[i][j][r] = 0.f;

    LOAD_STAGE(0, 0);

    #pragma unroll
    for (int ks = 0; ks < 8; ks++) {
        const int cur = ks & 1;
        if (ks < 7) {
            LOAD_STAGE(1 - cur, (ks + 1) * 32);
            CP_WAIT(1);
        } else {
            CP_WAIT(0);
        }
        __syncthreads();

        #pragma unroll
        for (int k8 = 0; k8 < 32; k8 += 8) {
            unsigned afr[4][4], bfr[4][2];
            #pragma unroll
            for (int mt = 0; mt < 4; mt++) {
                int row = wm * 64 + mt * 16;
                afr[mt][0] = As[(cur*128 + row + g    ) * PAD_B + k8 + t    ];
                afr[mt][1] = As[(cur*128 + row + 8 + g) * PAD_B + k8 + t    ];
                afr[mt][2] = As[(cur*128 + row + g    ) * PAD_B + k8 + 4 + t];
                afr[mt][3] = As[(cur*128 + row + 8 + g) * PAD_B + k8 + 4 + t];
            }
            #pragma unroll
            for (int nt = 0; nt < 4; nt++) {
                int col = wn * 32 + nt * 8;
                bfr[nt][0] = Bs[(cur*128 + col + g) * PAD_B + k8 + t    ];
                bfr[nt][1] = Bs[(cur*128 + col + g) * PAD_B + k8 + 4 + t];
            }
            #pragma unroll
            for (int mt = 0; mt < 4; mt++)
                #pragma unroll
                for (int nt = 0; nt < 4; nt++)
                    mma1688(acc[mt][nt], afr[mt], bfr[nt]);
        }
        __syncthreads();
    }
    #undef LOAD_STAGE

    const float* xp = x   + (size_t)b * CC * NQ;
    float*       op = out + (size_t)b * CC * NQ;
    #pragma unroll
    for (int mt = 0; mt < 4; mt++) {
        int o0 = ob + wm * 64 + mt * 16 + g;
        float bb0 = bo[o0], bb1 = bo[o0 + 8];
        #pragma unroll
        for (int nt = 0; nt < 4; nt++) {
            int n = nb + wn * 32 + nt * 8 + 2 * t;
            size_t base0 = (size_t)o0 * NQ + n;
            size_t base1 = (size_t)(o0 + 8) * NQ + n;
            float2 x0 = *(const float2*)&xp[base0];
            float2 x1 = *(const float2*)&xp[base1];
            float2 v0 = {acc[mt][nt][0] + bb0 + x0.x, acc[mt][nt][1] + bb0 + x0.y};
            float2 v1 = {acc[mt][nt][2] + bb1 + x1.x, acc[mt][nt][3] + bb1 + x1.y};
            *(float2*)&op[base0] = v0;
            *(float2*)&op[base1] = v1;
        }
    }
}

// ---------------------------------------------------------------------------
extern "C" void kernel_launch(void* const* d_in, const int* in_sizes, int n_in,
                              void* d_out, int out_size)
{
    const float* x    = (const float*)d_in[0];
    const int*   mask = (const int*)  d_in[1];
    const int*   aidx = (const int*)  d_in[2];
    const float* gsc  = (const float*)d_in[3];
    const float* gbi  = (const float*)d_in[4];
    const float* wq   = (const float*)d_in[5];
    const float* bq   = (const float*)d_in[6];
    const float* wk   = (const float*)d_in[7];
    const float* bk   = (const float*)d_in[8];
    const float* wv   = (const float*)d_in[9];
    const float* bv   = (const float*)d_in[10];
    const float* wo   = (const float*)d_in[11];
    const float* bo   = (const float*)d_in[12];
    float* out = (float*)d_out;

    cudaFuncSetAttribute(gemm_qkv, cudaFuncAttributeMaxDynamicSharedMemorySize,
                         QKV_SMEM);
    cudaFuncSetAttribute(gemm_out, cudaFuncAttributeMaxDynamicSharedMemorySize,
                         OUT_SMEM);

    gn_kernel<<<dim3(GROUPS, BB), 256>>>(x, gsc, gbi);

    gemm_qkv<<<dim3(NQ / 128, 6, BB), 256, QKV_SMEM>>>(wq, bq, wk, bk, wv, bv);

    int total_warps = BB * NQ;
    attn_kernel<<<total_warps * 32 / 256, 256>>>(mask, aidx);

    gemm_out<<<dim3(NQ / 128, CC / 128, BB), 256, OUT_SMEM>>>(wo, bo, x, out);
}